// round 9
// baseline (speedup 1.0000x reference)
#include <cuda_runtime.h>
#include <cstdint>

#define HW 262144
#define CHW 2621440          // 10*HW
#define MSGOFF 20971520      // 8*10*HW
#define NTILES 16384

#if defined(__CUDA_ARCH_FEAT_SM103_ALL) || defined(__CUDA_ARCH_FEAT_SM100_ALL) || \
    (defined(__CUDA_ARCH_SPECIFIC__) && (__CUDA_ARCH_SPECIFIC__ >= 1000))
#define HAS_TCGEN05 1
#else
#define HAS_TCGEN05 0
#endif

// g_fold float layout:
//  [16,6400)  tcgen05 path params (copied to smem bytes [64,25600)):
//    48..63 B2 ; 96..111 B4
//    256 W1hi[32x32 SW128] (row k=20 = folded bias1) ; 1280 W1lo
//    2304 W2hi[16x32] ; 2816 W2lo ; 3328 W3hi ; 4352 W3lo ; 5376 W4hi ; 5888 W4lo
//  [6400,8536) fallback params (round-2 layout):
//    +0 W1t[c][o] 640 ; +640 W3t 640 ; +1280 W2f[o][c pad12] 384 ; +1664 W4f 384
//    +2048 B1 32 ; +2080 B3 32 ; +2112 B2 12 ; +2124 B4 12
#define FBOFF 6400
__device__ float g_fold[8544];

__device__ __forceinline__ float tf32hi(float x){
    return __uint_as_float(__float_as_uint(x) & 0xFFFFE000u);
}

// ---------------------------------------------------------------------------
// prep kernel: fold BN into weights; emit both tcgen05 and fallback layouts
// ---------------------------------------------------------------------------
__global__ void fold_kernel(
    const float* __restrict__ w1,const float* __restrict__ g1,const float* __restrict__ b1,const float* __restrict__ m1,const float* __restrict__ v1,
    const float* __restrict__ w2,const float* __restrict__ g2,const float* __restrict__ b2,const float* __restrict__ m2,const float* __restrict__ v2,
    const float* __restrict__ w3,const float* __restrict__ g3,const float* __restrict__ b3,const float* __restrict__ m3,const float* __restrict__ v3,
    const float* __restrict__ w4,const float* __restrict__ g4,const float* __restrict__ b4,const float* __restrict__ m4,const float* __restrict__ v4)
{
    int tid = threadIdx.x;
    // --- tcgen05 swizzled hi/lo tiles ---
    for (int i = tid; i < 1024; i += 256){       // W1 (32 rows o, 32 cols k)
        int o = i >> 5, k = i & 31;
        float s = g1[o] * rsqrtf(v1[o] + 1e-5f);
        float v = 0.f;
        if (k < 20) v = w1[o*20 + k] * s;
        else if (k == 20) v = b1[o] - m1[o]*s;
        int byo = o*128 + k*4;
        int sw = byo ^ ((byo >> 3) & 0x70);
        float h = tf32hi(v);
        g_fold[256  + (sw >> 2)] = h;
        g_fold[1280 + (sw >> 2)] = v - h;
    }
    for (int i = tid; i < 1024; i += 256){       // W3
        int o = i >> 5, k = i & 31;
        float s = g3[o] * rsqrtf(v3[o] + 1e-5f);
        float v = 0.f;
        if (k < 20) v = w3[o*20 + k] * s;
        else if (k == 20) v = b3[o] - m3[o]*s;
        int byo = o*128 + k*4;
        int sw = byo ^ ((byo >> 3) & 0x70);
        float h = tf32hi(v);
        g_fold[3328 + (sw >> 2)] = h;
        g_fold[4352 + (sw >> 2)] = v - h;
    }
    for (int i = tid; i < 512; i += 256){        // W2 (16 rows n, 32 cols k)
        int n = i >> 5, k = i & 31;
        float v = 0.f;
        if (n < 10){ float s = g2[n]*rsqrtf(v2[n] + 1e-5f); v = w2[n*32 + k]*s; }
        int byo = n*128 + k*4;
        int sw = byo ^ ((byo >> 3) & 0x70);
        float h = tf32hi(v);
        g_fold[2304 + (sw >> 2)] = h;
        g_fold[2816 + (sw >> 2)] = v - h;
    }
    for (int i = tid; i < 512; i += 256){        // W4
        int n = i >> 5, k = i & 31;
        float v = 0.f;
        if (n < 10){ float s = g4[n]*rsqrtf(v4[n] + 1e-5f); v = w4[n*32 + k]*s; }
        int byo = n*128 + k*4;
        int sw = byo ^ ((byo >> 3) & 0x70);
        float h = tf32hi(v);
        g_fold[5376 + (sw >> 2)] = h;
        g_fold[5888 + (sw >> 2)] = v - h;
    }
    if (tid < 16){
        float val = 0.f;
        if (tid < 10){ float s = g2[tid]*rsqrtf(v2[tid] + 1e-5f); val = b2[tid] - m2[tid]*s; }
        g_fold[48 + tid] = val;
    } else if (tid < 32){
        int c = tid - 16;
        float val = 0.f;
        if (c < 10){ float s = g4[c]*rsqrtf(v4[c] + 1e-5f); val = b4[c] - m4[c]*s; }
        g_fold[96 + c] = val;
    }
    // --- fallback (round-2) layout ---
    for (int idx = tid; idx < 640; idx += 256){
        int c = idx >> 5, o = idx & 31;
        float s1 = g1[o] * rsqrtf(v1[o] + 1e-5f);
        g_fold[FBOFF + idx] = w1[o * 20 + c] * s1;
        float s3 = g3[o] * rsqrtf(v3[o] + 1e-5f);
        g_fold[FBOFF + 640 + idx] = w3[o * 20 + c] * s3;
    }
    for (int idx = tid; idx < 384; idx += 256){
        int o = idx / 12, c = idx % 12;
        float v2v = 0.f, v4v = 0.f;
        if (c < 10){
            float s2 = g2[c] * rsqrtf(v2[c] + 1e-5f); v2v = w2[c * 32 + o] * s2;
            float s4 = g4[c] * rsqrtf(v4[c] + 1e-5f); v4v = w4[c * 32 + o] * s4;
        }
        g_fold[FBOFF + 1280 + idx] = v2v;
        g_fold[FBOFF + 1664 + idx] = v4v;
    }
    if (tid < 32){
        float s1 = g1[tid] * rsqrtf(v1[tid] + 1e-5f);
        g_fold[FBOFF + 2048 + tid] = b1[tid] - m1[tid] * s1;
        float s3 = g3[tid] * rsqrtf(v3[tid] + 1e-5f);
        g_fold[FBOFF + 2080 + tid] = b3[tid] - m3[tid] * s3;
    } else if (tid < 44){
        int c = tid - 32;
        float val = 0.f;
        if (c < 10){ float s = g2[c]*rsqrtf(v2[c] + 1e-5f); val = b2[c] - m2[c]*s; }
        g_fold[FBOFF + 2112 + c] = val;
    } else if (tid < 56){
        int c = tid - 44;
        float val = 0.f;
        if (c < 10){ float s = g4[c]*rsqrtf(v4[c] + 1e-5f); val = b4[c] - m4[c]*s; }
        g_fold[FBOFF + 2124 + c] = val;
    }
}

// ---------------------------------------------------------------------------
// common helpers
// ---------------------------------------------------------------------------
__device__ __forceinline__ uint32_t s2u(const void* p){
    uint32_t a;
    asm("{ .reg .u64 t; cvta.to.shared.u64 t, %1; cvt.u32.u64 %0, t; }" : "=r"(a) : "l"(p));
    return a;
}
__device__ __forceinline__ float2 ffma2(float2 a, float2 b, float2 c) {
    float2 d;
    asm("{\n\t"
        ".reg .b64 ra, rb, rc;\n\t"
        "mov.b64 ra, {%2, %3};\n\t"
        "mov.b64 rb, {%4, %5};\n\t"
        "mov.b64 rc, {%6, %7};\n\t"
        "fma.rn.f32x2 rc, ra, rb, rc;\n\t"
        "mov.b64 {%0, %1}, rc;\n\t"
        "}"
        : "=f"(d.x), "=f"(d.y)
        : "f"(a.x), "f"(a.y), "f"(b.x), "f"(b.y), "f"(c.x), "f"(c.y));
    return d;
}

#if HAS_TCGEN05
// ---------------------------------------------------------------------------
// tcgen05 helpers (sm_103a-only pass)
// ---------------------------------------------------------------------------
__device__ __forceinline__ uint64_t sdesc(uint32_t addr){
    // SW128, version=1 (Blackwell), SBO=64, LBO=1 (K-major, 128B rows)
    return 0x4000404000010000ULL | (uint64_t)((addr >> 4) & 0x3FFF);
}
__device__ __forceinline__ void mma_tf32(uint32_t d, uint64_t a, uint64_t b, uint32_t idesc, uint32_t en){
    asm volatile("{\n\t"
        ".reg .pred p;\n\t"
        "setp.ne.u32 p, %4, 0;\n\t"
        "tcgen05.mma.cta_group::1.kind::tf32 [%0], %1, %2, %3, {%5, %5, %5, %5}, p;\n\t"
        "}"
        :: "r"(d), "l"(a), "l"(b), "r"(idesc), "r"(en), "r"(0u) : "memory");
}
template<int NK>
__device__ __forceinline__ void issue_stage(uint32_t d, uint64_t ah, uint64_t al,
                                            uint64_t bh, uint64_t bl, uint32_t idesc){
    uint32_t en = 0;
#pragma unroll
    for (int k = 0; k < NK; k++){ mma_tf32(d, ah + 2*k, bh + 2*k, idesc, en); en = 1; }
#pragma unroll
    for (int k = 0; k < NK; k++)  mma_tf32(d, ah + 2*k, bl + 2*k, idesc, 1);
#pragma unroll
    for (int k = 0; k < NK; k++)  mma_tf32(d, al + 2*k, bh + 2*k, idesc, 1);
}
__device__ __forceinline__ void tc_commit(uint32_t mbar){
    asm volatile("tcgen05.commit.cta_group::1.mbarrier::arrive::one.shared::cluster.b64 [%0];"
                 :: "r"(mbar) : "memory");
}
__device__ __forceinline__ void mbar_wait(uint32_t mbar, uint32_t ph){
    asm volatile("{\n\t"
        ".reg .pred P;\n\t"
        "LW%=:\n\t"
        "mbarrier.try_wait.parity.acquire.cta.shared::cta.b64 P, [%0], %1, 0x989680;\n\t"
        "@P bra LD%=;\n\t"
        "bra LW%=;\n\t"
        "LD%=:\n\t"
        "}" :: "r"(mbar), "r"(ph) : "memory");
}
__device__ __forceinline__ void fence_proxy(){ asm volatile("fence.proxy.async.shared::cta;" ::: "memory"); }
__device__ __forceinline__ void tc_fence_after(){ asm volatile("tcgen05.fence::after_thread_sync;" ::: "memory"); }
__device__ __forceinline__ void tc_wait_ld(){ asm volatile("tcgen05.wait::ld.sync.aligned;" ::: "memory"); }
__device__ __forceinline__ void wg_bar(int id){ asm volatile("bar.sync %0, 128;" :: "r"(id) : "memory"); }

__device__ __forceinline__ void ldtm32(uint32_t a, uint32_t* r){
    asm volatile("tcgen05.ld.sync.aligned.32x32b.x32.b32 "
        "{%0,%1,%2,%3,%4,%5,%6,%7,%8,%9,%10,%11,%12,%13,%14,%15,"
        "%16,%17,%18,%19,%20,%21,%22,%23,%24,%25,%26,%27,%28,%29,%30,%31}, [%32];"
        : "=r"(r[0]),"=r"(r[1]),"=r"(r[2]),"=r"(r[3]),"=r"(r[4]),"=r"(r[5]),"=r"(r[6]),"=r"(r[7]),
          "=r"(r[8]),"=r"(r[9]),"=r"(r[10]),"=r"(r[11]),"=r"(r[12]),"=r"(r[13]),"=r"(r[14]),"=r"(r[15]),
          "=r"(r[16]),"=r"(r[17]),"=r"(r[18]),"=r"(r[19]),"=r"(r[20]),"=r"(r[21]),"=r"(r[22]),"=r"(r[23]),
          "=r"(r[24]),"=r"(r[25]),"=r"(r[26]),"=r"(r[27]),"=r"(r[28]),"=r"(r[29]),"=r"(r[30]),"=r"(r[31])
        : "r"(a));
}
__device__ __forceinline__ void ldtm16(uint32_t a, uint32_t* r){
    asm volatile("tcgen05.ld.sync.aligned.32x32b.x16.b32 "
        "{%0,%1,%2,%3,%4,%5,%6,%7,%8,%9,%10,%11,%12,%13,%14,%15}, [%16];"
        : "=r"(r[0]),"=r"(r[1]),"=r"(r[2]),"=r"(r[3]),"=r"(r[4]),"=r"(r[5]),"=r"(r[6]),"=r"(r[7]),
          "=r"(r[8]),"=r"(r[9]),"=r"(r[10]),"=r"(r[11]),"=r"(r[12]),"=r"(r[13]),"=r"(r[14]),"=r"(r[15])
        : "r"(a));
}
__device__ __forceinline__ void sts4(uint32_t a, float x, float y, float z, float w){
    asm volatile("st.shared.v4.b32 [%0], {%1,%2,%3,%4};" :: "r"(a),"f"(x),"f"(y),"f"(z),"f"(w) : "memory");
}
// 20 data cols + constant-1 bias col (20) + zero pad (21..23)
__device__ __forceinline__ void store24(uint32_t rowh, uint32_t rowl, int sx, const float* v){
#pragma unroll
    for (int g = 0; g < 5; g++){
        uint32_t off = (uint32_t)((g ^ sx) * 16);
        float h0 = tf32hi(v[4*g]),   h1 = tf32hi(v[4*g+1]);
        float h2 = tf32hi(v[4*g+2]), h3 = tf32hi(v[4*g+3]);
        sts4(rowh + off, h0, h1, h2, h3);
        sts4(rowl + off, v[4*g]-h0, v[4*g+1]-h1, v[4*g+2]-h2, v[4*g+3]-h3);
    }
    uint32_t off = (uint32_t)((5 ^ sx) * 16);
    sts4(rowh + off, 1.f, 0.f, 0.f, 0.f);
    sts4(rowl + off, 0.f, 0.f, 0.f, 0.f);
}
__device__ __forceinline__ void store32(uint32_t rowh, uint32_t rowl, int sx, const float* v){
#pragma unroll
    for (int g = 0; g < 8; g++){
        uint32_t off = (uint32_t)((g ^ sx) * 16);
        float h0 = tf32hi(v[4*g]),   h1 = tf32hi(v[4*g+1]);
        float h2 = tf32hi(v[4*g+2]), h3 = tf32hi(v[4*g+3]);
        sts4(rowh + off, h0, h1, h2, h3);
        sts4(rowl + off, v[4*g]-h0, v[4*g+1]-h1, v[4*g+2]-h2, v[4*g+3]-h3);
    }
}
#else
// ---------------------------------------------------------------------------
// fallback helper: round-2 fused block (2 pixels, ffma2)
// ---------------------------------------------------------------------------
__device__ __forceinline__ void run_block_fb(
    const float2 (&xb)[2][20],
    const float* __restrict__ sWt, const float* __restrict__ sBa,
    const float* __restrict__ sW2, const float* __restrict__ sBb,
    float2 (&out2)[5][2])
{
#pragma unroll
    for (int cp = 0; cp < 5; cp++) {
        float2 bb = *reinterpret_cast<const float2*>(sBb + 2 * cp);
        out2[cp][0] = bb; out2[cp][1] = bb;
    }
#pragma unroll
    for (int ob = 0; ob < 32; ob += 4) {
        float2 b01 = *reinterpret_cast<const float2*>(sBa + ob);
        float2 b23 = *reinterpret_cast<const float2*>(sBa + ob + 2);
        float2 a00 = b01, a01 = b01, a10 = b23, a11 = b23;
#pragma unroll
        for (int c = 0; c < 20; c++) {
            float4 w = *reinterpret_cast<const float4*>(sWt + c * 32 + ob);
            float2 w01 = make_float2(w.x, w.y);
            float2 w23 = make_float2(w.z, w.w);
            a00 = ffma2(w01, xb[0][c], a00);
            a01 = ffma2(w01, xb[1][c], a01);
            a10 = ffma2(w23, xb[0][c], a10);
            a11 = ffma2(w23, xb[1][c], a11);
        }
        a00.x = fmaxf(a00.x, 0.f); a00.y = fmaxf(a00.y, 0.f);
        a01.x = fmaxf(a01.x, 0.f); a01.y = fmaxf(a01.y, 0.f);
        a10.x = fmaxf(a10.x, 0.f); a10.y = fmaxf(a10.y, 0.f);
        a11.x = fmaxf(a11.x, 0.f); a11.y = fmaxf(a11.y, 0.f);
#pragma unroll
        for (int j = 0; j < 4; j++) {
            float h0 = (j == 0) ? a00.x : (j == 1) ? a00.y : (j == 2) ? a10.x : a10.y;
            float h1 = (j == 0) ? a01.x : (j == 1) ? a01.y : (j == 2) ? a11.x : a11.y;
            float2 hb0 = make_float2(h0, h0);
            float2 hb1 = make_float2(h1, h1);
            const float* r = sW2 + (ob + j) * 12;
            float4 wa = *reinterpret_cast<const float4*>(r);
            float4 wb = *reinterpret_cast<const float4*>(r + 4);
            float2 wc = *reinterpret_cast<const float2*>(r + 8);
            float2 w0 = make_float2(wa.x, wa.y);
            float2 w1 = make_float2(wa.z, wa.w);
            float2 w2 = make_float2(wb.x, wb.y);
            float2 w3 = make_float2(wb.z, wb.w);
            out2[0][0] = ffma2(w0, hb0, out2[0][0]); out2[0][1] = ffma2(w0, hb1, out2[0][1]);
            out2[1][0] = ffma2(w1, hb0, out2[1][0]); out2[1][1] = ffma2(w1, hb1, out2[1][1]);
            out2[2][0] = ffma2(w2, hb0, out2[2][0]); out2[2][1] = ffma2(w2, hb1, out2[2][1]);
            out2[3][0] = ffma2(w3, hb0, out2[3][0]); out2[3][1] = ffma2(w3, hb1, out2[3][1]);
            out2[4][0] = ffma2(wc, hb0, out2[4][0]); out2[4][1] = ffma2(wc, hb1, out2[4][1]);
        }
    }
#pragma unroll
    for (int cp = 0; cp < 5; cp++) {
        out2[cp][0].x = fmaxf(out2[cp][0].x, 0.f); out2[cp][0].y = fmaxf(out2[cp][0].y, 0.f);
        out2[cp][1].x = fmaxf(out2[cp][1].x, 0.f); out2[cp][1].y = fmaxf(out2[cp][1].y, 0.f);
    }
}
#endif

// ---------------------------------------------------------------------------
// fused kernel (grid 148 x 512, 156672B dynamic smem in both variants)
// ---------------------------------------------------------------------------
__global__ void __launch_bounds__(512, 1) fused_kernel(
    const float* __restrict__ xf, const float* __restrict__ xh1,
    const float* __restrict__ xh2, float* __restrict__ out)
{
#if HAS_TCGEN05
    extern __shared__ char smem[];
    uint32_t sb = s2u(smem);
    int tid = threadIdx.x;
    int wg  = tid >> 7;
    int wt  = tid & 127;

    {   // params: g_fold floats [16,6400) -> smem bytes [64,25600)
        const float4* src = (const float4*)(g_fold + 16);
        float4* dst = (float4*)(smem + 64);
        for (int i = tid; i < 1596; i += 512) dst[i] = src[i];
    }
    if (tid < 32){
        asm volatile("tcgen05.alloc.cta_group::1.sync.aligned.shared::cta.b32 [%0], %1;"
                     :: "r"(sb), "r"(512u) : "memory");
        asm volatile("tcgen05.relinquish_alloc_permit.cta_group::1.sync.aligned;" ::: "memory");
    }
    if (tid >= 32 && tid < 36){
        uint32_t mb = sb + 8 + (uint32_t)(tid - 32) * 8;
        asm volatile("mbarrier.init.shared.b64 [%0], %1;" :: "r"(mb), "r"(1u) : "memory");
    }
    fence_proxy();
    __syncthreads();
    uint32_t tmem;
    asm volatile("ld.shared.b32 %0, [%1];" : "=r"(tmem) : "r"(sb));

    const float* bias2 = (const float*)(smem + 192);
    const float* bias4 = (const float*)(smem + 384);

    uint32_t mbar = sb + 8 + (uint32_t)wg * 8;
    uint32_t bufh = sb + 25600 + (uint32_t)wg * 32768;
    uint32_t bufl = bufh + 16384;
    uint64_t dAh = sdesc(bufh), dAl = sdesc(bufl);
    uint64_t dW1h = sdesc(sb + 1024),  uW1l = sdesc(sb + 5120);
    uint64_t dW2h = sdesc(sb + 9216),  uW2l = sdesc(sb + 11264);
    uint64_t dW3h = sdesc(sb + 13312), uW3l = sdesc(sb + 17408);
    uint64_t dW4h = sdesc(sb + 21504), uW4l = sdesc(sb + 23552);
    // idesc: dtype=F32(1)@4, atype=TF32(2)@7, btype=TF32(2)@10, N>>3@17, M>>4@24
    const uint32_t ID32 = (1u<<4) | (2u<<7) | (2u<<10) | (4u<<17) | (8u<<24);
    const uint32_t ID16 = (1u<<4) | (2u<<7) | (2u<<10) | (2u<<17) | (8u<<24);
    uint32_t tm1 = tmem + (uint32_t)wg * 64;
    uint32_t tm2 = tm1 + 32;
    uint32_t ph = 0;
    int bid = wg + 1;
    uint32_t rowh = bufh + (uint32_t)wt * 128;
    uint32_t rowl = bufl + (uint32_t)wt * 128;
    int sx = wt & 7;

    for (int t = blockIdx.x * 4 + wg; t < NTILES; t += gridDim.x * 4){
        size_t gbase = (size_t)(t >> 11) * CHW + (size_t)((t & 2047) << 7) + (size_t)wt;

        float a[20], rxf[10];
#pragma unroll
        for (int c = 0; c < 10; c++) a[c]      = xh1[gbase + (size_t)c * HW];
#pragma unroll
        for (int c = 0; c < 10; c++) a[10 + c] = xh2[gbase + (size_t)c * HW];
#pragma unroll
        for (int c = 0; c < 10; c++) rxf[c]    = xf [gbase + (size_t)c * HW];

        store24(rowh, rowl, sx, a);
        fence_proxy();
        wg_bar(bid);
        if (wt == 0){ tc_fence_after(); issue_stage<3>(tm1, dAh, dAl, dW1h, uW1l, ID32); tc_commit(mbar); }
        mbar_wait(mbar, ph); ph ^= 1;
        tc_fence_after();
        {   // epi1: h = relu(D1) (bias folded in via constant-1 channel)
            uint32_t d[32]; ldtm32(tm1, d); tc_wait_ld();
            float h[32];
#pragma unroll
            for (int j = 0; j < 32; j++) h[j] = fmaxf(__uint_as_float(d[j]), 0.f);
            store32(rowh, rowl, sx, h);
        }
        fence_proxy();
        wg_bar(bid);
        if (wt == 0){ tc_fence_after(); issue_stage<4>(tm2, dAh, dAl, dW2h, uW2l, ID16); tc_commit(mbar); }
        mbar_wait(mbar, ph); ph ^= 1;
        tc_fence_after();
        float msg[10];
        {   // epi2: message out
            uint32_t d[16]; ldtm16(tm2, d); tc_wait_ld();
#pragma unroll
            for (int j = 0; j < 10; j++) msg[j] = fmaxf(__uint_as_float(d[j]) + bias2[j], 0.f);
        }
#pragma unroll
        for (int j = 0; j < 10; j++) out[MSGOFF + gbase + (size_t)j * HW] = msg[j];
        {
            float a2[20];
#pragma unroll
            for (int c = 0; c < 10; c++){ a2[c] = rxf[c]; a2[10 + c] = msg[c]; }
            store24(rowh, rowl, sx, a2);
        }
        fence_proxy();
        wg_bar(bid);
        if (wt == 0){ tc_fence_after(); issue_stage<3>(tm1, dAh, dAl, dW3h, uW3l, ID32); tc_commit(mbar); }
        mbar_wait(mbar, ph); ph ^= 1;
        tc_fence_after();
        {   // epi3
            uint32_t d[32]; ldtm32(tm1, d); tc_wait_ld();
            float h[32];
#pragma unroll
            for (int j = 0; j < 32; j++) h[j] = fmaxf(__uint_as_float(d[j]), 0.f);
            store32(rowh, rowl, sx, h);
        }
        fence_proxy();
        wg_bar(bid);
        if (wt == 0){ tc_fence_after(); issue_stage<4>(tm2, dAh, dAl, dW4h, uW4l, ID16); tc_commit(mbar); }
        mbar_wait(mbar, ph); ph ^= 1;
        tc_fence_after();
        {   // epi4: xf_new out
            uint32_t d[16]; ldtm16(tm2, d); tc_wait_ld();
#pragma unroll
            for (int j = 0; j < 10; j++)
                out[gbase + (size_t)j * HW] = fmaxf(__uint_as_float(d[j]) + bias4[j], 0.f);
        }
    }
    __syncthreads();
    if (tid < 32){
        asm volatile("tcgen05.dealloc.cta_group::1.sync.aligned.b32 %0, %1;" :: "r"(tmem), "r"(512u));
    }
#else
    // ------------------- fallback: round-2 ffma2 path -------------------
    extern __shared__ char smem[];
    float* sf = (float*)smem;
    {
        const float4* src = reinterpret_cast<const float4*>(g_fold + FBOFF);
        float4* dst = reinterpret_cast<float4*>(sf);
        for (int i = threadIdx.x; i < 534; i += 512) dst[i] = src[i];
    }
    __syncthreads();
    const float* sW1t = sf;
    const float* sW3t = sf + 640;
    const float* sW2f = sf + 1280;
    const float* sW4f = sf + 1664;
    const float* sB1  = sf + 2048;
    const float* sB3  = sf + 2080;
    const float* sB2  = sf + 2112;
    const float* sB4  = sf + 2124;

    const int stride = gridDim.x * 512;
    for (int t = blockIdx.x * 512 + threadIdx.x; t < 1048576; t += stride){
        int b  = t >> 17;
        int hw = (t & 0x1FFFF) << 1;
        size_t base = (size_t)b * CHW + hw;
        const float* ph1 = xh1 + base;
        const float* ph2 = xh2 + base;
        const float* pf  = xf  + base;
        float* po_new = out + base;
        float* po_msg = out + (size_t)MSGOFF + base;

        float2 xb[2][20];
#pragma unroll
        for (int c = 0; c < 10; c++) {
            float2 v = *reinterpret_cast<const float2*>(ph1 + (size_t)c * HW);
            xb[0][c] = make_float2(v.x, v.x);
            xb[1][c] = make_float2(v.y, v.y);
        }
#pragma unroll
        for (int c = 0; c < 10; c++) {
            float2 v = *reinterpret_cast<const float2*>(ph2 + (size_t)c * HW);
            xb[0][10 + c] = make_float2(v.x, v.x);
            xb[1][10 + c] = make_float2(v.y, v.y);
        }

        float2 msg2[5][2];
        run_block_fb(xb, sW1t, sB1, sW2f, sB2, msg2);

#pragma unroll
        for (int cp = 0; cp < 5; cp++) {
            float2 m0 = msg2[cp][0], m1 = msg2[cp][1];
            *reinterpret_cast<float2*>(po_msg + (size_t)(2 * cp)     * HW) = make_float2(m0.x, m1.x);
            *reinterpret_cast<float2*>(po_msg + (size_t)(2 * cp + 1) * HW) = make_float2(m0.y, m1.y);
            xb[0][10 + 2 * cp]     = make_float2(m0.x, m0.x);
            xb[0][10 + 2 * cp + 1] = make_float2(m0.y, m0.y);
            xb[1][10 + 2 * cp]     = make_float2(m1.x, m1.x);
            xb[1][10 + 2 * cp + 1] = make_float2(m1.y, m1.y);
        }
#pragma unroll
        for (int c = 0; c < 10; c++) {
            float2 v = *reinterpret_cast<const float2*>(pf + (size_t)c * HW);
            xb[0][c] = make_float2(v.x, v.x);
            xb[1][c] = make_float2(v.y, v.y);
        }

        float2 r2[5][2];
        run_block_fb(xb, sW3t, sB3, sW4f, sB4, r2);

#pragma unroll
        for (int cp = 0; cp < 5; cp++) {
            float2 r0 = r2[cp][0], r1 = r2[cp][1];
            *reinterpret_cast<float2*>(po_new + (size_t)(2 * cp)     * HW) = make_float2(r0.x, r1.x);
            *reinterpret_cast<float2*>(po_new + (size_t)(2 * cp + 1) * HW) = make_float2(r0.y, r1.y);
        }
    }
#endif
}

extern "C" void kernel_launch(void* const* d_in, const int* in_sizes, int n_in,
                              void* d_out, int out_size) {
    const float* xf  = (const float*)d_in[0];
    const float* xh1 = (const float*)d_in[1];
    const float* xh2 = (const float*)d_in[2];

    fold_kernel<<<1, 256>>>(
        (const float*)d_in[3],  (const float*)d_in[4],  (const float*)d_in[5],
        (const float*)d_in[6],  (const float*)d_in[7],
        (const float*)d_in[8],  (const float*)d_in[9],  (const float*)d_in[10],
        (const float*)d_in[11], (const float*)d_in[12],
        (const float*)d_in[13], (const float*)d_in[14], (const float*)d_in[15],
        (const float*)d_in[16], (const float*)d_in[17],
        (const float*)d_in[18], (const float*)d_in[19], (const float*)d_in[20],
        (const float*)d_in[21], (const float*)d_in[22]);

    cudaFuncSetAttribute(fused_kernel, cudaFuncAttributeMaxDynamicSharedMemorySize, 156672);
    fused_kernel<<<148, 512, 156672>>>(xf, xh1, xh2, (float*)d_out);
}